// round 3
// baseline (speedup 1.0000x reference)
#include <cuda_runtime.h>
#include <cstdint>

// CondFilterT: per row b (BATCH=16384):
//   e = table[inp[b,0]]  (64 fp32)   -> out[b, 0:64] raw
//   for c in 0..49: v = table[inp[b,1+c]]
//     filtered = v * dot(e, v) / (||e|| * ||v||^2)   -> out[b, 64 + 64c : 64 + 64(c+1)]
//
// One warp per row, lane owns float2 (dims 2*lane, 2*lane+1).
// Two warp-reduced sums per condition (sum v^2, sum e*v); single rsqrtf per row.

#define CF_BATCH  16384
#define CF_NCONDS 50
#define CF_EMB    64
#define CF_ROWLEN (CF_EMB * (1 + CF_NCONDS))   // 3264 floats per output row

__global__ __launch_bounds__(256)
void condfilter_kernel(const int* __restrict__ inp,
                       const float* __restrict__ table,
                       float* __restrict__ out)
{
    const unsigned FULL = 0xFFFFFFFFu;
    const int gwarp = (blockIdx.x * blockDim.x + threadIdx.x) >> 5;
    const int lane  = threadIdx.x & 31;
    if (gwarp >= CF_BATCH) return;

    // ---- load the 51 indices for this row into lane registers ----
    const int* row = inp + (size_t)gwarp * (1 + CF_NCONDS);
    const int idx_lo = row[lane];                                   // indices 0..31
    const int idx_hi = (lane < (1 + CF_NCONDS - 32)) ? row[32 + lane] : 0; // 32..50

    // ---- event embedding + inverse norm ----
    const int e_idx = __shfl_sync(FULL, idx_lo, 0);
    const float2 e = __ldg((const float2*)(table + (size_t)e_idx * CF_EMB) + lane);
    float ss = e.x * e.x + e.y * e.y;
    #pragma unroll
    for (int o = 16; o > 0; o >>= 1) ss += __shfl_xor_sync(FULL, ss, o);
    const float e_inv = rsqrtf(ss);

    float2* orow = (float2*)(out + (size_t)gwarp * CF_ROWLEN);
    orow[lane] = e;   // raw (un-normalized) event embedding, 256B coalesced

    // ---- conditions, 5 at a time for load/shuffle ILP ----
    #pragma unroll 2
    for (int c0 = 0; c0 < CF_NCONDS; c0 += 5) {
        float2 cv[5];
        #pragma unroll
        for (int u = 0; u < 5; u++) {
            const int j = 1 + c0 + u;                 // uniform across warp
            const int v = (j < 32) ? idx_lo : idx_hi; // uniform branch
            const int cidx = __shfl_sync(FULL, v, j & 31);
            cv[u] = __ldg((const float2*)(table + (size_t)cidx * CF_EMB) + lane);
        }

        float s1[5], s2[5];
        #pragma unroll
        for (int u = 0; u < 5; u++) {
            s1[u] = cv[u].x * cv[u].x + cv[u].y * cv[u].y;  // ||v||^2 partial
            s2[u] = e.x * cv[u].x + e.y * cv[u].y;          // dot(e, v) partial
        }

        // interleaved butterfly reductions: 10 independent shfl chains/level
        #pragma unroll
        for (int o = 16; o > 0; o >>= 1) {
            #pragma unroll
            for (int u = 0; u < 5; u++) {
                s1[u] += __shfl_xor_sync(FULL, s1[u], o);
                s2[u] += __shfl_xor_sync(FULL, s2[u], o);
            }
        }

        #pragma unroll
        for (int u = 0; u < 5; u++) {
            const float sc = (s2[u] * e_inv) / s1[u];   // score / ||v||
            float2 w;
            w.x = cv[u].x * sc;
            w.y = cv[u].y * sc;
            orow[32 + (size_t)(c0 + u) * 32 + lane] = w;  // 256B coalesced
        }
    }
}

extern "C" void kernel_launch(void* const* d_in, const int* in_sizes, int n_in,
                              void* d_out, int out_size)
{
    const int*   inp   = (const int*)d_in[0];     // (16384, 51) int32
    const float* table = (const float*)d_in[1];   // (100002, 64) float32
    float*       out   = (float*)d_out;           // (16384, 3264) float32

    // 8 warps (= 8 rows) per 256-thread block
    const int rows_per_block = 256 / 32;
    const int grid = (CF_BATCH + rows_per_block - 1) / rows_per_block;  // 2048
    condfilter_kernel<<<grid, 256>>>(inp, table, out);
}

// round 5
// speedup vs baseline: 1.2301x; 1.2301x over previous
#include <cuda_runtime.h>
#include <cstdint>

// CondFilterT: per row b (BATCH=16384):
//   e = table[inp[b,0]]  (64 fp32)   -> out[b, 0:64] raw
//   for c in 0..49: v = table[inp[b,1+c]]
//     filtered = v * dot(e,v) / (||e|| * ||v||^2)  -> out[b, 64+64c : 64+64(c+1)]
//
// R4: float4 per lane, 16 lanes per row => ONE WARP PROCESSES 2 ROWS
// (one per half-warp). Halves LDG/STG/SHFL/FMA instruction count per row
// vs R3 (which was L1tex/issue bound at 75.7% / 61.9%).

#define CF_BATCH  16384
#define CF_NCONDS 50
#define CF_EMB    64
#define CF_ROWLEN (CF_EMB * (1 + CF_NCONDS))   // 3264 floats per output row

__global__ __launch_bounds__(256)
void condfilter_kernel(const int* __restrict__ inp,
                       const float* __restrict__ table,
                       float* __restrict__ out)
{
    const unsigned FULL = 0xFFFFFFFFu;
    const int lane   = threadIdx.x & 31;
    const int half   = lane >> 4;          // which half-warp (row within pair)
    const int hl     = lane & 15;          // lane within half-warp
    const int gwarp  = (blockIdx.x * blockDim.x + threadIdx.x) >> 5;
    const int rowid  = gwarp * 2 + half;   // this half-warp's batch row
    if (rowid >= CF_BATCH) return;

    // ---- load the 51 indices for this row into 4 lane registers ----
    // index j lives in reg (j/16) of lane (j%16) of this half-warp
    const int* irow = inp + (size_t)rowid * (1 + CF_NCONDS);
    const int idx_a = irow[hl];                         // j = 0..15
    const int idx_b = irow[16 + hl];                    // j = 16..31
    const int idx_c = irow[32 + hl];                    // j = 32..47
    const int idx_d = (hl < 3) ? irow[48 + hl] : 0;     // j = 48..50

    const int hbase = half << 4;   // source-lane base for this half-warp

    // ---- event embedding + inverse norm (reduce over 16 lanes) ----
    const int e_idx = __shfl_sync(FULL, idx_a, hbase);  // j = 0
    const float4 e = __ldg((const float4*)(table + (size_t)e_idx * CF_EMB) + hl);
    float ss = e.x * e.x + e.y * e.y + e.z * e.z + e.w * e.w;
    #pragma unroll
    for (int o = 8; o > 0; o >>= 1) ss += __shfl_xor_sync(FULL, ss, o);
    const float e_inv = rsqrtf(ss);

    float4* orow = (float4*)(out + (size_t)rowid * CF_ROWLEN);
    __stcs(orow + hl, e);   // raw event embedding, 256B coalesced, evict-first

    // ---- conditions, 5 at a time for load/shuffle ILP ----
    #pragma unroll 2
    for (int c0 = 0; c0 < CF_NCONDS; c0 += 5) {
        float4 cv[5];
        #pragma unroll
        for (int u = 0; u < 5; u++) {
            const int j = 1 + c0 + u;                       // uniform across warp
            const int v = (j < 16) ? idx_a
                        : (j < 32) ? idx_b
                        : (j < 48) ? idx_c : idx_d;          // uniform selects
            const int cidx = __shfl_sync(FULL, v, hbase + (j & 15));
            cv[u] = __ldg((const float4*)(table + (size_t)cidx * CF_EMB) + hl);
        }

        float s1[5], s2[5];
        #pragma unroll
        for (int u = 0; u < 5; u++) {
            s1[u] = cv[u].x * cv[u].x + cv[u].y * cv[u].y
                  + cv[u].z * cv[u].z + cv[u].w * cv[u].w;          // ||v||^2
            s2[u] = e.x * cv[u].x + e.y * cv[u].y
                  + e.z * cv[u].z + e.w * cv[u].w;                  // dot(e, v)
        }

        // interleaved butterfly reductions over 16 lanes (stay within half)
        #pragma unroll
        for (int o = 8; o > 0; o >>= 1) {
            #pragma unroll
            for (int u = 0; u < 5; u++) {
                s1[u] += __shfl_xor_sync(FULL, s1[u], o);
                s2[u] += __shfl_xor_sync(FULL, s2[u], o);
            }
        }

        #pragma unroll
        for (int u = 0; u < 5; u++) {
            const float sc = (s2[u] * e_inv) / s1[u];   // score / ||v||
            float4 w;
            w.x = cv[u].x * sc;
            w.y = cv[u].y * sc;
            w.z = cv[u].z * sc;
            w.w = cv[u].w * sc;
            __stcs(orow + 16 + (size_t)(c0 + u) * 16 + hl, w);  // 256B coalesced
        }
    }
}

extern "C" void kernel_launch(void* const* d_in, const int* in_sizes, int n_in,
                              void* d_out, int out_size)
{
    const int*   inp   = (const int*)d_in[0];     // (16384, 51) int32
    const float* table = (const float*)d_in[1];   // (100002, 64) float32
    float*       out   = (float*)d_out;           // (16384, 3264) float32

    // 8 warps/block, 2 rows/warp -> 16 rows per 256-thread block
    const int rows_per_block = (256 / 32) * 2;
    const int grid = (CF_BATCH + rows_per_block - 1) / rows_per_block;  // 1024
    condfilter_kernel<<<grid, 256>>>(inp, table, out);
}